// round 9
// baseline (speedup 1.0000x reference)
#include <cuda_runtime.h>
#include <cuda_fp16.h>

// GCN link predictor, CSR gather formulation, fp16 gather rows + fp16 a2.
// 8 launches: init -> [convert|gemm1] -> lookback-scan -> csr_fill ->
//             gather1 -> gemm2 -> gather2 -> logits
//
// NOTE: __device__ scratch arrays are ONLY referenced inside device code
// (host-side use of the symbol is UB and silently corrupts via ATS on GB300).

#define N_NODES 100000
#define MAX_E   1600000
#define D_IN    32
#define D_HID   64
#define D_OUT   32

#define LBCH    1024                              // elements per scan chunk
#define NLB     ((N_NODES + LBCH - 1) / LBCH)     // 98 chunks

__device__ __align__(16) int    g_cnt [N_NODES];
__device__ __align__(16) int    g_off [N_NODES];
__device__ __align__(16) float  g_dinv[N_NODES];
__device__ __align__(16) float  g_h1  [N_NODES * D_HID];
__device__ __align__(16) __half g_h1h [N_NODES * D_HID];
__device__ __align__(16) float  g_a1  [N_NODES * D_HID];
__device__ __align__(16) float  g_h2  [N_NODES * D_OUT];
__device__ __align__(16) __half g_h2h [N_NODES * D_OUT];
__device__ __align__(16) __half g_a2h [N_NODES * D_OUT];
__device__ __align__(16) int    g_src [MAX_E];
__device__ __align__(16) int    g_dst [MAX_E];
__device__ __align__(16) int    g_pos [MAX_E];
__device__ __align__(16) float2 g_csr [MAX_E];    // (.x = src bits, .y = norm)
__device__ unsigned long long   g_lb  [NLB];      // lookback state: val<<2 | flag
__device__ unsigned int         g_ticket;
__device__ int                  g_is64;

// ---------------------------------------------------------------------------
// 0) init: zero counts + scan state + dtype detect
// ---------------------------------------------------------------------------
__global__ void k_init(const void* __restrict__ ei, int n) {
    int i = blockIdx.x * blockDim.x + threadIdx.x;
    if (i < n) g_cnt[i] = 0;
    if (i < NLB) g_lb[i] = 0ull;
    if (i == 0) {
        g_ticket = 0u;
        const long long* p = (const long long*)ei;
        int is64 = 1;
        #pragma unroll
        for (int k = 0; k < 8; k++) {
            long long v = p[k];
            if (v < 0 || v >= N_NODES) is64 = 0;
        }
        g_is64 = is64;
    }
}

// ---------------------------------------------------------------------------
// 1) FUSED: convert indices + degree histogram  ||  GEMM1 (independent work)
//    blocks [0, cb) do convert; blocks [cb, cb+gb) do gemm1
// ---------------------------------------------------------------------------
__global__ void k_convert_gemm1(const void* __restrict__ ei, int E,
                                const float* __restrict__ x,
                                const float* __restrict__ W1, int n, int cb) {
    __shared__ float sW[D_IN * D_HID];
    __shared__ float sx[4 * D_IN];
    int tid = threadIdx.x;

    if ((int)blockIdx.x < cb) {
        // ---- convert + histogram ----
        int i = blockIdx.x * blockDim.x + tid;
        if (i >= 2 * E) return;
        int v;
        if (g_is64) v = (int)((const long long*)ei)[i];
        else        v = ((const int*)ei)[i];
        v = min(max(v, 0), N_NODES - 1);
        if (i < E) {
            g_src[i] = v;
        } else {
            int e = i - E;
            g_dst[e] = v;
            g_pos[e] = atomicAdd(&g_cnt[v], 1);
        }
        return;
    }

    // ---- gemm1: h1 = x @ W1 (fp32 + fp16 copy) ----
    int bid = blockIdx.x - cb;
    for (int i = tid; i < D_IN * D_HID; i += 256) sW[i] = W1[i];
    int node0 = bid * 4;
    if (tid < 4 * D_IN) {
        int nn = node0 + tid / D_IN;
        sx[tid] = (nn < n) ? x[nn * D_IN + (tid % D_IN)] : 0.0f;
    }
    __syncthreads();
    int local = tid >> 6;
    int j     = tid & 63;
    int node  = node0 + local;
    if (node < n) {
        float acc = 0.0f;
        #pragma unroll
        for (int k = 0; k < D_IN; k++)
            acc = fmaf(sx[local * D_IN + k], sW[k * D_HID + j], acc);
        g_h1 [node * D_HID + j] = acc;
        g_h1h[node * D_HID + j] = __float2half(acc);
    }
}

// ---------------------------------------------------------------------------
// 2) single-launch decoupled-lookback exclusive scan (+ fused dinv)
//    flag: 0 = invalid, 1 = partial, 2 = prefix; value packed in bits [2:64)
// ---------------------------------------------------------------------------
__global__ void k_scan(int n) {     // grid = NLB, block = 256
    __shared__ int sh[256];
    __shared__ int s_bid;
    __shared__ int s_excl;
    int t = threadIdx.x;
    if (t == 0) s_bid = (int)atomicAdd(&g_ticket, 1u);
    __syncthreads();
    int bid  = s_bid;
    int base = bid * LBCH + t * 4;

    int4 c4 = make_int4(0, 0, 0, 0);
    if (base + 3 < n) {
        c4 = *reinterpret_cast<const int4*>(g_cnt + base);
    } else {
        int* cp = (int*)&c4;
        #pragma unroll
        for (int k = 0; k < 4; k++) cp[k] = (base + k < n) ? g_cnt[base + k] : 0;
    }
    int lsum = c4.x + c4.y + c4.z + c4.w;
    sh[t] = lsum;
    __syncthreads();
    #pragma unroll
    for (int d = 1; d < 256; d <<= 1) {
        int v = (t >= d) ? sh[t - d] : 0;
        __syncthreads();
        sh[t] += v;
        __syncthreads();
    }
    int total = sh[255];
    int texcl = sh[t] - lsum;

    if (t == 0) {
        atomicExch(&g_lb[bid], ((unsigned long long)total << 2) | 1ull);  // partial
        long long excl = 0;
        int j = bid - 1;
        while (j >= 0) {
            unsigned long long v;
            do { v = atomicAdd(&g_lb[j], 0ull); } while ((v & 3ull) == 0ull);
            excl += (long long)(v >> 2);
            if ((v & 3ull) == 2ull) break;
            j--;
        }
        atomicExch(&g_lb[bid],
                   ((unsigned long long)(excl + total) << 2) | 2ull);     // prefix
        s_excl = (int)excl;
    }
    __syncthreads();
    int run = s_excl + texcl;

    int off[4];
    off[0] = run;
    off[1] = off[0] + c4.x;
    off[2] = off[1] + c4.y;
    off[3] = off[2] + c4.z;
    if (base + 3 < n) {
        *reinterpret_cast<int4*>(g_off + base) = *reinterpret_cast<int4*>(off);
        float4 dv = make_float4(rsqrtf((float)(c4.x + 1)), rsqrtf((float)(c4.y + 1)),
                                rsqrtf((float)(c4.z + 1)), rsqrtf((float)(c4.w + 1)));
        *reinterpret_cast<float4*>(g_dinv + base) = dv;
    } else {
        int* cp = (int*)&c4;
        #pragma unroll
        for (int k = 0; k < 4; k++) if (base + k < n) {
            g_off[base + k]  = off[k];
            g_dinv[base + k] = rsqrtf((float)(cp[k] + 1));
        }
    }
}

// ---------------------------------------------------------------------------
// 3) CSR fill, atomic-free
// ---------------------------------------------------------------------------
__global__ void k_csr_fill(int E) {
    int e = blockIdx.x * blockDim.x + threadIdx.x;
    if (e >= E) return;
    int s = g_src[e];
    int d = g_dst[e];
    int pos = g_off[d] + g_pos[e];
    g_csr[pos] = make_float2(__int_as_float(s), g_dinv[s] * g_dinv[d]);
}

// ---------------------------------------------------------------------------
// fp16 accumulate helpers
// ---------------------------------------------------------------------------
__device__ __forceinline__ void add_row8(float* acc, uint4 r, float w) {
    __half2* h = reinterpret_cast<__half2*>(&r);
    #pragma unroll
    for (int k = 0; k < 4; k++) {
        float2 f = __half22float2(h[k]);
        acc[2 * k + 0] = fmaf(f.x, w, acc[2 * k + 0]);
        acc[2 * k + 1] = fmaf(f.y, w, acc[2 * k + 1]);
    }
}

__device__ __forceinline__ void add_row4(float* acc, uint2 r, float w) {
    __half2* h = reinterpret_cast<__half2*>(&r);
    #pragma unroll
    for (int k = 0; k < 2; k++) {
        float2 f = __half22float2(h[k]);
        acc[2 * k + 0] = fmaf(f.x, w, acc[2 * k + 0]);
        acc[2 * k + 1] = fmaf(f.y, w, acc[2 * k + 1]);
    }
}

// ---------------------------------------------------------------------------
// 4) gather layer 1: 8 threads/node, 8 cols each; two-phase batches
//    (all shuffles -> all 8 loads in flight -> all FMAs)
// ---------------------------------------------------------------------------
__global__ void k_gather1(const float* __restrict__ b1, int n) {
    int lane = threadIdx.x & 31;
    int t    = lane & 7;
    int node = blockIdx.x * 32 + (threadIdx.x >> 3);
    if (node >= n) return;
    unsigned gmask = 0xFFu << (lane & 24);
    int beg = g_off[node];
    int end = beg + g_cnt[node];
    const uint4* rows = reinterpret_cast<const uint4*>(g_h1h);  // 8 uint4 / row
    float acc[8];
    #pragma unroll
    for (int k = 0; k < 8; k++) acc[k] = 0.0f;
    int nfull = (end - beg) & ~7;
    int i = beg;
    for (; i < beg + nfull; i += 8) {
        float2 e = g_csr[i + t];
        float ex[8], ey[8];
        #pragma unroll
        for (int k = 0; k < 8; k++) {
            ex[k] = __shfl_sync(gmask, e.x, k, 8);
            ey[k] = __shfl_sync(gmask, e.y, k, 8);
        }
        uint4 r[8];
        #pragma unroll
        for (int k = 0; k < 8; k++)
            r[k] = rows[__float_as_int(ex[k]) * 8 + t];
        #pragma unroll
        for (int k = 0; k < 8; k++)
            add_row8(acc, r[k], ey[k]);
    }
    if (i < end) {
        float2 e = (i + t < end) ? g_csr[i + t] : make_float2(0.f, 0.f);
        int rem = end - i;
        #pragma unroll
        for (int k = 0; k < 8; k++) {
            if (k >= rem) break;
            float ex = __shfl_sync(gmask, e.x, k, 8);
            float ey = __shfl_sync(gmask, e.y, k, 8);
            uint4 r = rows[__float_as_int(ex) * 8 + t];
            add_row8(acc, r, ey);
        }
    }
    float di = g_dinv[node];
    float d2 = di * di;
    const float* selfp = g_h1 + node * D_HID + t * 8;
    const float* bp    = b1 + t * 8;
    float* outp        = g_a1 + node * D_HID + t * 8;
    #pragma unroll
    for (int half = 0; half < 2; half++) {
        float4 s4 = *reinterpret_cast<const float4*>(selfp + half * 4);
        float4 b4 = *reinterpret_cast<const float4*>(bp + half * 4);
        float4 o;
        o.x = fmaxf(fmaf(s4.x, d2, acc[half * 4 + 0]) + b4.x, 0.f);
        o.y = fmaxf(fmaf(s4.y, d2, acc[half * 4 + 1]) + b4.y, 0.f);
        o.z = fmaxf(fmaf(s4.z, d2, acc[half * 4 + 2]) + b4.z, 0.f);
        o.w = fmaxf(fmaf(s4.w, d2, acc[half * 4 + 3]) + b4.w, 0.f);
        *reinterpret_cast<float4*>(outp + half * 4) = o;
    }
}

// ---------------------------------------------------------------------------
// 5) GEMM2: h2 = a1 @ W2 (fp32 + fp16 copy)
// ---------------------------------------------------------------------------
__global__ void k_gemm2(const float* __restrict__ W2, int n) {
    __shared__ float sW[D_HID * D_OUT];
    __shared__ float sx[8 * D_HID];
    int tid = threadIdx.x;
    for (int i = tid; i < D_HID * D_OUT; i += 256) sW[i] = W2[i];
    int node0 = blockIdx.x * 8;
    for (int i = tid; i < 8 * D_HID; i += 256) {
        int nn = node0 + i / D_HID;
        sx[i] = (nn < n) ? g_a1[nn * D_HID + (i % D_HID)] : 0.0f;
    }
    __syncthreads();
    int local = tid >> 5;
    int j     = tid & 31;
    int node  = node0 + local;
    if (node < n) {
        float acc = 0.0f;
        #pragma unroll
        for (int k = 0; k < D_HID; k++)
            acc = fmaf(sx[local * D_HID + k], sW[k * D_OUT + j], acc);
        g_h2 [node * D_OUT + j] = acc;
        g_h2h[node * D_OUT + j] = __float2half(acc);
    }
}

// ---------------------------------------------------------------------------
// 6) gather layer 2: 8 threads/node, 4 cols each; two-phase batches;
//    fp16 output (feeds logits only)
// ---------------------------------------------------------------------------
__global__ void k_gather2(const float* __restrict__ b2, int n) {
    int lane = threadIdx.x & 31;
    int t    = lane & 7;
    int node = blockIdx.x * 32 + (threadIdx.x >> 3);
    if (node >= n) return;
    unsigned gmask = 0xFFu << (lane & 24);
    int beg = g_off[node];
    int end = beg + g_cnt[node];
    const uint2* rows = reinterpret_cast<const uint2*>(g_h2h);  // 8 uint2 / row
    float acc[4];
    #pragma unroll
    for (int k = 0; k < 4; k++) acc[k] = 0.0f;
    int nfull = (end - beg) & ~7;
    int i = beg;
    for (; i < beg + nfull; i += 8) {
        float2 e = g_csr[i + t];
        float ex[8], ey[8];
        #pragma unroll
        for (int k = 0; k < 8; k++) {
            ex[k] = __shfl_sync(gmask, e.x, k, 8);
            ey[k] = __shfl_sync(gmask, e.y, k, 8);
        }
        uint2 r[8];
        #pragma unroll
        for (int k = 0; k < 8; k++)
            r[k] = rows[__float_as_int(ex[k]) * 8 + t];
        #pragma unroll
        for (int k = 0; k < 8; k++)
            add_row4(acc, r[k], ey[k]);
    }
    if (i < end) {
        float2 e = (i + t < end) ? g_csr[i + t] : make_float2(0.f, 0.f);
        int rem = end - i;
        #pragma unroll
        for (int k = 0; k < 8; k++) {
            if (k >= rem) break;
            float ex = __shfl_sync(gmask, e.x, k, 8);
            float ey = __shfl_sync(gmask, e.y, k, 8);
            uint2 r = rows[__float_as_int(ex) * 8 + t];
            add_row4(acc, r, ey);
        }
    }
    float di = g_dinv[node];
    float d2 = di * di;
    float4 s4 = *reinterpret_cast<const float4*>(g_h2 + node * D_OUT + t * 4);
    float4 b4 = *reinterpret_cast<const float4*>(b2 + t * 4);
    float o0 = fmaf(s4.x, d2, acc[0]) + b4.x;
    float o1 = fmaf(s4.y, d2, acc[1]) + b4.y;
    float o2 = fmaf(s4.z, d2, acc[2]) + b4.z;
    float o3 = fmaf(s4.w, d2, acc[3]) + b4.w;
    __half2 h0 = __floats2half2_rn(o0, o1);
    __half2 h1 = __floats2half2_rn(o2, o3);
    uint2 packed;
    packed.x = *reinterpret_cast<unsigned*>(&h0);
    packed.y = *reinterpret_cast<unsigned*>(&h1);
    reinterpret_cast<uint2*>(g_a2h)[node * 8 + t] = packed;
}

// ---------------------------------------------------------------------------
// 7) per-edge logits: one thread per edge, full fp16 rows, MLP=8
// ---------------------------------------------------------------------------
__global__ void k_logits(float* __restrict__ out, int E) {
    int e = blockIdx.x * blockDim.x + threadIdx.x;
    if (e >= E) return;
    int s = g_src[e];
    int d = g_dst[e];
    const uint4* rows = reinterpret_cast<const uint4*>(g_a2h);  // 4 uint4 / row
    uint4 rs[4], rd[4];
    #pragma unroll
    for (int k = 0; k < 4; k++) rs[k] = rows[s * 4 + k];
    #pragma unroll
    for (int k = 0; k < 4; k++) rd[k] = rows[d * 4 + k];
    float p = 0.0f;
    #pragma unroll
    for (int k = 0; k < 4; k++) {
        __half2* hs = reinterpret_cast<__half2*>(&rs[k]);
        __half2* hd = reinterpret_cast<__half2*>(&rd[k]);
        #pragma unroll
        for (int j = 0; j < 4; j++) {
            float2 fs = __half22float2(hs[j]);
            float2 fd = __half22float2(hd[j]);
            p = fmaf(fs.x, fd.x, p);
            p = fmaf(fs.y, fd.y, p);
        }
    }
    out[e] = p;
}

// ---------------------------------------------------------------------------
extern "C" void kernel_launch(void* const* d_in, const int* in_sizes, int n_in,
                              void* d_out, int out_size) {
    const float* x   = (const float*)d_in[0];
    const void*  ei  = d_in[1];
    const float* W1  = (const float*)d_in[2];
    const float* b1  = (const float*)d_in[3];
    const float* W2  = (const float*)d_in[4];
    const float* b2  = (const float*)d_in[5];
    float*       out = (float*)d_out;

    int N = in_sizes[0] / D_IN; if (N > N_NODES) N = N_NODES;
    int E = in_sizes[1] / 2;    if (E > MAX_E)   E = MAX_E;
    const int T = 256;

    k_init<<<(N + T - 1) / T, T>>>(ei, N);

    int cb = (2 * E + T - 1) / T;          // convert blocks
    int gb = (N + 3) / 4;                  // gemm1 blocks
    k_convert_gemm1<<<cb + gb, T>>>(ei, E, x, W1, N, cb);

    k_scan<<<NLB, T>>>(N);
    k_csr_fill<<<(E + T - 1) / T, T>>>(E);

    k_gather1<<<(N + 31) / 32, T>>>(b1, N);
    k_gemm2<<<(N + 7) / 8, T>>>(W2, N);
    k_gather2<<<(N + 31) / 32, T>>>(b2, N);

    k_logits<<<(E + T - 1) / T, T>>>(out, E);
}